// round 4
// baseline (speedup 1.0000x reference)
#include <cuda_runtime.h>
#include <cuda_fp16.h>
#include <cstdint>

#define N_DIM 512

// ---------------- scratch ----------------
__device__ float g_P[(size_t)100000 * 128];   // P[node][0..63]=s-scores, [64..127]=o-scores

// ---------------- helpers ----------------
__device__ __forceinline__ uint32_t smem_u32(const void* p) {
    uint32_t a;
    asm("{ .reg .u64 t; cvta.to.shared.u64 t, %1; cvt.u32.u64 %0, t; }" : "=r"(a) : "l"(p));
    return a;
}
__device__ __forceinline__ void ldsm4(uint32_t r[4], uint32_t a) {
    asm volatile("ldmatrix.sync.aligned.m8n8.x4.shared.b16 {%0,%1,%2,%3}, [%4];"
                 : "=r"(r[0]), "=r"(r[1]), "=r"(r[2]), "=r"(r[3]) : "r"(a));
}
__device__ __forceinline__ void hmma16816(float d[4], const uint32_t a[4], uint32_t b0, uint32_t b1) {
    asm volatile("mma.sync.aligned.m16n8k16.row.col.f32.f16.f16.f32 "
                 "{%0,%1,%2,%3},{%4,%5,%6,%7},{%8,%9},{%0,%1,%2,%3};"
                 : "+f"(d[0]), "+f"(d[1]), "+f"(d[2]), "+f"(d[3])
                 : "r"(a[0]), "r"(a[1]), "r"(a[2]), "r"(a[3]), "r"(b0), "r"(b1));
}
__device__ __forceinline__ void cvt16(const float4 v[4], uint4 h[2]) {
    #pragma unroll
    for (int i = 0; i < 2; i++) {
        __half2 a0 = __floats2half2_rn(v[2*i].x,   v[2*i].y);
        __half2 a1 = __floats2half2_rn(v[2*i].z,   v[2*i].w);
        __half2 a2 = __floats2half2_rn(v[2*i+1].x, v[2*i+1].y);
        __half2 a3 = __floats2half2_rn(v[2*i+1].z, v[2*i+1].w);
        h[i].x = *(uint32_t*)&a0; h[i].y = *(uint32_t*)&a1;
        h[i].z = *(uint32_t*)&a2; h[i].w = *(uint32_t*)&a3;
    }
}

// smem: A[2][128][72] + B[2][128][72] halfs (pad 72 -> ldmatrix conflict-free)
#define LROW 72
#define BUF_HALFS (128 * LROW)
#define SMEM_BYTES (4 * BUF_HALFS * 2)   // 73728

// ---------------- kernel 1: P = emb @ B^T via mma.sync, A & B fp16 ----------------
__global__ __launch_bounds__(512) void gemm_kernel(const float* __restrict__ emb,
                                                   const float* __restrict__ W,
                                                   int n_nodes) {
    extern __shared__ __half sm[];
    const int tid = threadIdx.x;
    const int lane = tid & 31;
    const int wid = tid >> 5;
    const int ctaM = blockIdx.x * 128;

    __half* AS = sm;
    __half* BS = sm + 2 * BUF_HALFS;
    const uint32_t ASb = smem_u32(sm);
    const uint32_t BSb = ASb + 2 * BUF_HALFS * 2;

    // producers: 4 threads per row, each 16 cols of the 64-col K-chunk
    const int prow = tid >> 2;
    const int pcol = (tid & 3) * 16;
    int arow = ctaM + prow;
    if (arow >= n_nodes) arow = n_nodes - 1;
    const float4* ag = (const float4*)(emb + (size_t)arow * N_DIM + pcol);
    // B row prow: n<64 -> Ws row n, else Wo row n-64 (second half of W row)
    const float4* bg = (const float4*)(W + ((prow < 64)
                        ? (size_t)prow * 1024
                        : (size_t)(prow - 64) * 1024 + 512) + pcol);

    float4 va[4], vb[4];
    auto LOAD = [&](int c) {
        #pragma unroll
        for (int i = 0; i < 4; i++) va[i] = ag[c * 16 + i];
        #pragma unroll
        for (int i = 0; i < 4; i++) vb[i] = bg[c * 16 + i];
    };
    auto STORE = [&](int buf) {
        uint4 h[2];
        const int o = buf * BUF_HALFS + prow * LROW + pcol;
        cvt16(va, h);
        *(uint4*)&AS[o]     = h[0];
        *(uint4*)&AS[o + 8] = h[1];
        cvt16(vb, h);
        *(uint4*)&BS[o]     = h[0];
        *(uint4*)&BS[o + 8] = h[1];
    };

    float acc[2][4][4];
    #pragma unroll
    for (int i = 0; i < 2; i++)
        #pragma unroll
        for (int j = 0; j < 4; j++)
            #pragma unroll
            for (int k = 0; k < 4; k++) acc[i][j][k] = 0.0f;

    const int wm = wid & 3;   // 4 M-tiles of 32
    const int wn = wid >> 2;  // 4 N-tiles of 32

    LOAD(0);
    STORE(0);
    __syncthreads();

    for (int c = 0; c < 8; c++) {
        const int buf = c & 1;
        if (c < 7) LOAD(c + 1);   // LDGs in flight during mma below

        const uint32_t a_r = ASb + buf * (BUF_HALFS * 2);
        const uint32_t b_r = BSb + buf * (BUF_HALFS * 2);

        #pragma unroll
        for (int ks = 0; ks < 4; ks++) {
            uint32_t afr[2][4], bfr[2][4];
            const int acol = ks * 16 + (lane >> 4) * 8;
            #pragma unroll
            for (int mt = 0; mt < 2; mt++) {
                const int ar = wm * 32 + mt * 16 + (lane & 15);
                ldsm4(afr[mt], a_r + (uint32_t)(ar * LROW + acol) * 2);
            }
            const int bk = ks * 16 + ((lane >> 3) & 1) * 8;
            #pragma unroll
            for (int nt = 0; nt < 2; nt++) {
                const int br = wn * 32 + nt * 16 + (lane & 7) + ((lane >> 4) & 1) * 8;
                ldsm4(bfr[nt], b_r + (uint32_t)(br * LROW + bk) * 2);
            }
            #pragma unroll
            for (int mt = 0; mt < 2; mt++)
                #pragma unroll
                for (int nf = 0; nf < 4; nf++)
                    hmma16816(acc[mt][nf], afr[mt],
                              bfr[nf >> 1][(nf & 1) * 2], bfr[nf >> 1][(nf & 1) * 2 + 1]);
        }
        if (c < 7) {
            __syncthreads();
            STORE((c + 1) & 1);
            __syncthreads();
        }
    }

    // epilogue: write P
    #pragma unroll
    for (int mt = 0; mt < 2; mt++) {
        const int r0 = ctaM + wm * 32 + mt * 16 + (lane >> 2);
        const int r1 = r0 + 8;
        #pragma unroll
        for (int nf = 0; nf < 4; nf++) {
            const int col = wn * 32 + nf * 8 + (lane & 3) * 2;
            if (r0 < n_nodes)
                *(float2*)&g_P[(size_t)r0 * 128 + col] = make_float2(acc[mt][nf][0], acc[mt][nf][1]);
            if (r1 < n_nodes)
                *(float2*)&g_P[(size_t)r1 * 128 + col] = make_float2(acc[mt][nf][2], acc[mt][nf][3]);
        }
    }
}

// ---------------- kernel 2: per-triple gather-combine ----------------
__global__ __launch_bounds__(256) void gather_kernel(const int* __restrict__ triples,
                                                     const float* __restrict__ b,
                                                     float* __restrict__ out, int n) {
    int t = blockIdx.x * blockDim.x + threadIdx.x;
    if (t >= n) return;
    int s = triples[t];
    int r = triples[n + t];
    int o = triples[2 * n + t];
    out[t] = __ldg(&g_P[(size_t)s * 128 + r]) + __ldg(&g_P[(size_t)o * 128 + 64 + r]) + __ldg(&b[r]);
}

extern "C" void kernel_launch(void* const* d_in, const int* in_sizes, int n_in,
                              void* d_out, int out_size)
{
    const float* emb     = (const float*)d_in[0];
    const float* W       = (const float*)d_in[1];
    const float* b       = (const float*)d_in[2];
    const int*   triples = (const int*)d_in[3];
    float*       out     = (float*)d_out;

    int n_nodes = in_sizes[0] / N_DIM;   // 100000
    int n_tr    = in_sizes[3] / 3;       // 200000

    static bool attr_set = false;
    if (!attr_set) {
        cudaFuncSetAttribute(gemm_kernel, cudaFuncAttributeMaxDynamicSharedMemorySize, SMEM_BYTES);
        attr_set = true;
    }

    gemm_kernel<<<(n_nodes + 127) / 128, 512, SMEM_BYTES>>>(emb, W, n_nodes);
    gather_kernel<<<(n_tr + 255) / 256, 256>>>(triples, b, out, n_tr);
}

// round 5
// speedup vs baseline: 2.0684x; 2.0684x over previous
#include <cuda_runtime.h>
#include <cuda_fp16.h>
#include <cstdint>

#define N_DIM 512

// ---------------- scratch ----------------
__device__ __half g_Bh[128 * 512];            // fp16 W: rows 0..63 = Ws, 64..127 = Wo
__device__ float  g_P[(size_t)100000 * 128];  // P[node][0..63]=s-scores, [64..127]=o-scores

// ---------------- smem geometry ----------------
#define A_PAD 80                               // floats per A row (64 data + 16 pad) -> conflict-free LDS.128
#define B_PAD 80                               // halfs  per B row (64 data + 16 pad) -> conflict-free LDS.64
#define A_STAGE_B (128 * A_PAD * 4)            // 40960
#define B_STAGE_B (128 * B_PAD * 2)            // 20480
#define STAGE_B   (A_STAGE_B + B_STAGE_B)      // 61440
#define STAGES 3
#define SMEM_BYTES (STAGES * STAGE_B)          // 184320

// ---------------- helpers ----------------
__device__ __forceinline__ uint32_t smem_u32(const void* p) {
    uint32_t a;
    asm("{ .reg .u64 t; cvta.to.shared.u64 t, %1; cvt.u32.u64 %0, t; }" : "=r"(a) : "l"(p));
    return a;
}
__device__ __forceinline__ void cp16(uint32_t saddr, const void* g) {
    asm volatile("cp.async.cg.shared.global [%0], [%1], 16;" :: "r"(saddr), "l"(g));
}
__device__ __forceinline__ void cp_commit() {
    asm volatile("cp.async.commit_group;" ::: "memory");
}
template <int N>
__device__ __forceinline__ void cp_wait() {
    asm volatile("cp.async.wait_group %0;" :: "n"(N) : "memory");
}
__device__ __forceinline__ void hmma16816(float d[4], const uint32_t a[4], uint32_t b0, uint32_t b1) {
    asm volatile("mma.sync.aligned.m16n8k16.row.col.f32.f16.f16.f32 "
                 "{%0,%1,%2,%3},{%4,%5,%6,%7},{%8,%9},{%0,%1,%2,%3};"
                 : "+f"(d[0]), "+f"(d[1]), "+f"(d[2]), "+f"(d[3])
                 : "r"(a[0]), "r"(a[1]), "r"(a[2]), "r"(a[3]), "r"(b0), "r"(b1));
}
__device__ __forceinline__ uint32_t pack_h2(float x, float y) {
    __half2 h = __floats2half2_rn(x, y);
    return *reinterpret_cast<uint32_t*>(&h);
}

// ---------------- kernel 0: W fp32 -> fp16, reorder to [128][512] ----------------
__global__ __launch_bounds__(256) void prep_kernel(const float* __restrict__ W) {
    int idx = blockIdx.x * blockDim.x + threadIdx.x;   // 32768 threads, 2 elems each
    int i = idx * 2;
    if (i >= 128 * 512) return;
    int n = i >> 9, k = i & 511;
    const float* src = (n < 64) ? (W + n * 1024 + k) : (W + (n - 64) * 1024 + 512 + k);
    float2 v = *(const float2*)src;
    *(__half2*)&g_Bh[i] = __floats2half2_rn(v.x, v.y);
}

// ---------------- kernel 1: P = emb @ B^T, cp.async 3-stage pipeline ----------------
__global__ __launch_bounds__(512, 1) void gemm_kernel(const float* __restrict__ emb, int n_nodes) {
    extern __shared__ char smem[];
    const uint32_t sb = smem_u32(smem);
    const int tid = threadIdx.x;
    const int lane = tid & 31;
    const int wid = tid >> 5;
    const int wm = wid & 3;     // M-tile of 32 (CTA M=128)
    const int wn = wid >> 2;    // N-tile of 32 (CTA N=128)
    const int ctaM = blockIdx.x * 128;

    // producer: issue one K-chunk (64 wide) into pipeline slot c%3
    auto ISSUE = [&](int c) {
        const uint32_t base = sb + (c % 3) * STAGE_B;
        // A: 128 rows x 64 fp32 = 2048 x 16B granules, 4 per thread
        #pragma unroll
        for (int i = 0; i < 4; i++) {
            int g = tid + i * 512;
            int row = g >> 4, col = g & 15;
            int ar = ctaM + row;
            if (ar >= n_nodes) ar = n_nodes - 1;
            cp16(base + row * (A_PAD * 4) + col * 16,
                 emb + (size_t)ar * N_DIM + c * 64 + col * 4);
        }
        // B: 128 rows x 64 fp16 = 1024 x 16B granules, 2 per thread
        #pragma unroll
        for (int i = 0; i < 2; i++) {
            int g = tid + i * 512;
            int row = g >> 3, col = g & 7;
            cp16(base + A_STAGE_B + row * (B_PAD * 2) + col * 16,
                 g_Bh + row * N_DIM + c * 64 + col * 8);
        }
    };

    float acc[2][4][4];
    #pragma unroll
    for (int i = 0; i < 2; i++)
        #pragma unroll
        for (int j = 0; j < 4; j++)
            #pragma unroll
            for (int k = 0; k < 4; k++) acc[i][j][k] = 0.0f;

    ISSUE(0); cp_commit();
    ISSUE(1); cp_commit();

    const int q = lane & 3;          // quad id -> physical k group {4q..4q+3}
    const int octr = lane >> 2;      // 0..7

    for (int c = 0; c < 8; c++) {
        if (c + 2 < 8) ISSUE(c + 2);
        cp_commit();                 // empty groups at tail keep positional count
        cp_wait<2>();                // stage c resident
        __syncthreads();

        const uint32_t aBase = sb + (c % 3) * STAGE_B;
        const uint32_t bBase = aBase + A_STAGE_B;

        #pragma unroll
        for (int ks = 0; ks < 4; ks++) {
            // ---- A frags: sigma-permuted (LDS.128 covers physical k 4q..4q+3) ----
            uint32_t afr[2][4];
            #pragma unroll
            for (int mt = 0; mt < 2; mt++) {
                const int r0 = wm * 32 + mt * 16 + octr;
                const float4 v0 = *(const float4*)(smem + ((c % 3) * STAGE_B) + r0 * (A_PAD * 4) + ks * 64 + q * 16);
                const float4 v1 = *(const float4*)(smem + ((c % 3) * STAGE_B) + (r0 + 8) * (A_PAD * 4) + ks * 64 + q * 16);
                afr[mt][0] = pack_h2(v0.x, v0.y);   // logical k 2q,2q+1   <- phys 4q,4q+1
                afr[mt][1] = pack_h2(v1.x, v1.y);
                afr[mt][2] = pack_h2(v0.z, v0.w);   // logical k 2q+8,2q+9 <- phys 4q+2,4q+3
                afr[mt][3] = pack_h2(v1.z, v1.w);
            }
            // ---- B frags: one LDS.64 per n8 frag, same sigma ----
            uint2 bfr[4];
            #pragma unroll
            for (int nf = 0; nf < 4; nf++) {
                const int n = wn * 32 + nf * 8 + octr;
                bfr[nf] = *(const uint2*)(smem + ((c % 3) * STAGE_B) + A_STAGE_B + n * (B_PAD * 2) + ks * 32 + q * 8);
            }
            #pragma unroll
            for (int mt = 0; mt < 2; mt++)
                #pragma unroll
                for (int nf = 0; nf < 4; nf++)
                    hmma16816(acc[mt][nf], afr[mt], bfr[nf].x, bfr[nf].y);
        }
        __syncthreads();
    }

    // ---- epilogue: write P ----
    #pragma unroll
    for (int mt = 0; mt < 2; mt++) {
        const int r0 = ctaM + wm * 32 + mt * 16 + (lane >> 2);
        const int r1 = r0 + 8;
        #pragma unroll
        for (int nf = 0; nf < 4; nf++) {
            const int col = wn * 32 + nf * 8 + (lane & 3) * 2;
            if (r0 < n_nodes)
                *(float2*)&g_P[(size_t)r0 * 128 + col] = make_float2(acc[mt][nf][0], acc[mt][nf][1]);
            if (r1 < n_nodes)
                *(float2*)&g_P[(size_t)r1 * 128 + col] = make_float2(acc[mt][nf][2], acc[mt][nf][3]);
        }
    }
}

// ---------------- kernel 2: per-triple gather-combine ----------------
__global__ __launch_bounds__(256) void gather_kernel(const int* __restrict__ triples,
                                                     const float* __restrict__ b,
                                                     float* __restrict__ out, int n) {
    int t = blockIdx.x * blockDim.x + threadIdx.x;
    if (t >= n) return;
    int s = triples[t];
    int r = triples[n + t];
    int o = triples[2 * n + t];
    out[t] = __ldg(&g_P[(size_t)s * 128 + r]) + __ldg(&g_P[(size_t)o * 128 + 64 + r]) + __ldg(&b[r]);
}

extern "C" void kernel_launch(void* const* d_in, const int* in_sizes, int n_in,
                              void* d_out, int out_size)
{
    const float* emb     = (const float*)d_in[0];
    const float* W       = (const float*)d_in[1];
    const float* b       = (const float*)d_in[2];
    const int*   triples = (const int*)d_in[3];
    float*       out     = (float*)d_out;

    int n_nodes = in_sizes[0] / N_DIM;   // 100000
    int n_tr    = in_sizes[3] / 3;       // 200000

    cudaFuncSetAttribute(gemm_kernel, cudaFuncAttributeMaxDynamicSharedMemorySize, SMEM_BYTES);

    prep_kernel<<<128, 256>>>(W);
    gemm_kernel<<<(n_nodes + 127) / 128, 512, SMEM_BYTES>>>(emb, n_nodes);
    gather_kernel<<<(n_tr + 255) / 256, 256>>>(triples, b, out, n_tr);
}

// round 7
// speedup vs baseline: 2.2676x; 1.0963x over previous
#include <cuda_runtime.h>
#include <cuda_fp16.h>
#include <cstdint>

#define N_DIM 512

// ---------------- scratch ----------------
__device__ __half g_Bh[128 * 512];            // fp16 W: rows 0..63 = Ws, 64..127 = Wo
__device__ float  g_P[(size_t)100000 * 128];  // P[node][0..63]=s-scores, [64..127]=o-scores

// ---------------- smem geometry ----------------
#define A_PAD 80                               // floats per A row -> conflict-free LDS.128
#define B_PAD 80                               // halfs per B row  -> conflict-free LDS.64
#define A_STAGE_B (128 * A_PAD * 4)            // 40960
#define B_STAGE_B (128 * B_PAD * 2)            // 20480
#define STAGE_B   (A_STAGE_B + B_STAGE_B)      // 61440
#define SMEM_BYTES (3 * STAGE_B)               // 184320

// ---------------- helpers ----------------
__device__ __forceinline__ uint32_t smem_u32(const void* p) {
    uint32_t a;
    asm("{ .reg .u64 t; cvta.to.shared.u64 t, %1; cvt.u32.u64 %0, t; }" : "=r"(a) : "l"(p));
    return a;
}
__device__ __forceinline__ void cp16(uint32_t saddr, const void* g) {
    asm volatile("cp.async.cg.shared.global [%0], [%1], 16;" :: "r"(saddr), "l"(g));
}
__device__ __forceinline__ void cp_commit() {
    asm volatile("cp.async.commit_group;" ::: "memory");
}
template <int N>
__device__ __forceinline__ void cp_wait() {
    asm volatile("cp.async.wait_group %0;" :: "n"(N) : "memory");
}
__device__ __forceinline__ void hmma16816(float d[4], const uint32_t a[4], uint32_t b0, uint32_t b1) {
    asm volatile("mma.sync.aligned.m16n8k16.row.col.f32.f16.f16.f32 "
                 "{%0,%1,%2,%3},{%4,%5,%6,%7},{%8,%9},{%0,%1,%2,%3};"
                 : "+f"(d[0]), "+f"(d[1]), "+f"(d[2]), "+f"(d[3])
                 : "r"(a[0]), "r"(a[1]), "r"(a[2]), "r"(a[3]), "r"(b0), "r"(b1));
}
__device__ __forceinline__ uint32_t pack_h2(float x, float y) {
    __half2 h = __floats2half2_rn(x, y);
    return *reinterpret_cast<uint32_t*>(&h);
}

// ---------------- kernel 0: W fp32 -> fp16, reorder to [128][512] ----------------
__global__ __launch_bounds__(128) void prep_kernel(const float* __restrict__ W) {
    int i = (blockIdx.x * 128 + threadIdx.x) * 2;
    if (i >= 128 * 512) return;
    int n = i >> 9, k = i & 511;
    const float* src = (n < 64) ? (W + n * 1024 + k) : (W + (n - 64) * 1024 + 512 + k);
    float2 v = *(const float2*)src;
    *(__half2*)&g_Bh[i] = __floats2half2_rn(v.x, v.y);
}

// ---------------- kernel 1: persistent P = emb @ B^T, continuous cp.async stream ----------------
__global__ __launch_bounds__(512, 1) void gemm_kernel(const float* __restrict__ emb,
                                                      int n_nodes, int ntiles, int grid) {
    extern __shared__ char smem[];
    const uint32_t sb = smem_u32(smem);
    const int tid = threadIdx.x;
    const int lane = tid & 31;
    const int wid = tid >> 5;
    const int wm = wid & 3;     // M-tile of 32
    const int wn = wid >> 2;    // N-tile of 32
    const int bid = blockIdx.x;

    const int ntiles_mine = (ntiles - bid + grid - 1) / grid;
    const int gtot = ntiles_mine * 8;           // total chunks in my stream

    // producer: global chunk g -> (tile, kchunk), into slot g%3
    auto ISSUE = [&](int g) {
        if (g >= gtot) return;
        const int tile = bid + (g >> 3) * grid;
        const int c = g & 7;
        const int ctaM = tile * 128;
        const uint32_t base = sb + (g % 3) * STAGE_B;
        #pragma unroll
        for (int i = 0; i < 4; i++) {           // A: 2048 granules of 16B
            int gr = tid + i * 512;
            int row = gr >> 4, col = gr & 15;
            int ar = ctaM + row;
            if (ar >= n_nodes) ar = n_nodes - 1;
            cp16(base + row * (A_PAD * 4) + col * 16,
                 emb + (size_t)ar * N_DIM + c * 64 + col * 4);
        }
        #pragma unroll
        for (int i = 0; i < 2; i++) {           // B: 1024 granules (L2-resident)
            int gr = tid + i * 512;
            int row = gr >> 3, col = gr & 7;
            cp16(base + A_STAGE_B + row * (B_PAD * 2) + col * 16,
                 g_Bh + row * N_DIM + c * 64 + col * 8);
        }
    };

    float acc[2][4][4];
    #pragma unroll
    for (int i = 0; i < 2; i++)
        #pragma unroll
        for (int j = 0; j < 4; j++)
            #pragma unroll
            for (int k = 0; k < 4; k++) acc[i][j][k] = 0.0f;

    ISSUE(0); cp_commit();
    ISSUE(1); cp_commit();

    const int q = lane & 3;
    const int octr = lane >> 2;

    for (int g = 0; g < gtot; g++) {
        // pending groups entering here: {g, g+1}. wait<1> -> group g complete.
        cp_wait<1>();
        // barrier: (a) everyone's stage-g copies now visible to all threads,
        //          (b) all warps finished consuming chunk g-1, so slot (g+2)%3
        //              == (g-1)%3 is free to overwrite after this point.
        __syncthreads();

        const uint32_t slot = (g % 3) * STAGE_B;
        #pragma unroll
        for (int ks = 0; ks < 4; ks++) {
            uint32_t afr[2][4];
            #pragma unroll
            for (int mt = 0; mt < 2; mt++) {
                const int r0 = wm * 32 + mt * 16 + octr;
                const float4 v0 = *(const float4*)(smem + slot + r0 * (A_PAD * 4) + ks * 64 + q * 16);
                const float4 v1 = *(const float4*)(smem + slot + (r0 + 8) * (A_PAD * 4) + ks * 64 + q * 16);
                afr[mt][0] = pack_h2(v0.x, v0.y);
                afr[mt][1] = pack_h2(v1.x, v1.y);
                afr[mt][2] = pack_h2(v0.z, v0.w);
                afr[mt][3] = pack_h2(v1.z, v1.w);
            }
            uint2 bfr[4];
            #pragma unroll
            for (int nf = 0; nf < 4; nf++) {
                const int n = wn * 32 + nf * 8 + octr;
                bfr[nf] = *(const uint2*)(smem + slot + A_STAGE_B + n * (B_PAD * 2) + ks * 32 + q * 8);
            }
            #pragma unroll
            for (int mt = 0; mt < 2; mt++)
                #pragma unroll
                for (int nf = 0; nf < 4; nf++)
                    hmma16816(acc[mt][nf], afr[mt], bfr[nf].x, bfr[nf].y);
        }

        // refill the pipeline AFTER consuming (slot proven free by this iteration's barrier)
        ISSUE(g + 2);
        cp_commit();              // unconditional: empty groups keep positional count

        if ((g & 7) == 7) {
            // epilogue for this tile (overlaps in-flight copies of next tile)
            const int ctaM = (bid + (g >> 3) * grid) * 128;
            #pragma unroll
            for (int mt = 0; mt < 2; mt++) {
                const int r0 = ctaM + wm * 32 + mt * 16 + (lane >> 2);
                const int r1 = r0 + 8;
                #pragma unroll
                for (int nf = 0; nf < 4; nf++) {
                    const int col = wn * 32 + nf * 8 + (lane & 3) * 2;
                    if (r0 < n_nodes)
                        *(float2*)&g_P[(size_t)r0 * 128 + col] = make_float2(acc[mt][nf][0], acc[mt][nf][1]);
                    if (r1 < n_nodes)
                        *(float2*)&g_P[(size_t)r1 * 128 + col] = make_float2(acc[mt][nf][2], acc[mt][nf][3]);
                    acc[mt][nf][0] = acc[mt][nf][1] = acc[mt][nf][2] = acc[mt][nf][3] = 0.0f;
                }
            }
        }
    }
}

// ---------------- kernel 2: per-triple gather-combine ----------------
__global__ __launch_bounds__(256) void gather_kernel(const int* __restrict__ triples,
                                                     const float* __restrict__ b,
                                                     float* __restrict__ out, int n) {
    int t = blockIdx.x * blockDim.x + threadIdx.x;
    if (t >= n) return;
    int s = triples[t];
    int r = triples[n + t];
    int o = triples[2 * n + t];
    out[t] = __ldg(&g_P[(size_t)s * 128 + r]) + __ldg(&g_P[(size_t)o * 128 + 64 + r]) + __ldg(&b[r]);
}

extern "C" void kernel_launch(void* const* d_in, const int* in_sizes, int n_in,
                              void* d_out, int out_size)
{
    const float* emb     = (const float*)d_in[0];
    const float* W       = (const float*)d_in[1];
    const float* b       = (const float*)d_in[2];
    const int*   triples = (const int*)d_in[3];
    float*       out     = (float*)d_out;

    int n_nodes = in_sizes[0] / N_DIM;   // 100000
    int n_tr    = in_sizes[3] / 3;       // 200000
    int ntiles  = (n_nodes + 127) / 128;

    static int nsm = 0;
    if (nsm == 0) {
        cudaDeviceGetAttribute(&nsm, cudaDevAttrMultiProcessorCount, 0);
        cudaFuncSetAttribute(gemm_kernel, cudaFuncAttributeMaxDynamicSharedMemorySize, SMEM_BYTES);
    }
    int grid = (ntiles < nsm) ? ntiles : nsm;

    prep_kernel<<<256, 128>>>(W);
    gemm_kernel<<<grid, 512, SMEM_BYTES>>>(emb, n_nodes, ntiles, grid);
    gather_kernel<<<(n_tr + 255) / 256, 256>>>(triples, b, out, n_tr);
}

// round 8
// speedup vs baseline: 2.5666x; 1.1319x over previous
#include <cuda_runtime.h>
#include <cuda_fp16.h>
#include <cstdint>

#define N_DIM 512

// ---------------- scratch ----------------
__device__ __half g_Bh[128 * 512];            // fp16 W: rows 0..63 = Ws, 64..127 = Wo
__device__ float  g_P[(size_t)100000 * 128];  // P[node][0..63]=s-scores, [64..127]=o-scores

// ---------------- smem geometry (2-stage, M=256 tile) ----------------
#define A_PAD 80                               // floats per A row (320B) -> conflict-free LDS.128
#define B_PAD 80                               // halfs per B row (160B)
#define A_STAGE_B (256 * A_PAD * 4)            // 81920
#define B_STAGE_B (128 * B_PAD * 2)            // 20480
#define B_OFF     (2 * A_STAGE_B)              // 163840
#define SMEM_BYTES (2 * A_STAGE_B + 2 * B_STAGE_B)  // 204800

// ---------------- helpers ----------------
__device__ __forceinline__ uint32_t smem_u32(const void* p) {
    uint32_t a;
    asm("{ .reg .u64 t; cvta.to.shared.u64 t, %1; cvt.u32.u64 %0, t; }" : "=r"(a) : "l"(p));
    return a;
}
__device__ __forceinline__ void cp16(uint32_t saddr, const void* g) {
    asm volatile("cp.async.cg.shared.global [%0], [%1], 16;" :: "r"(saddr), "l"(g));
}
__device__ __forceinline__ void cp_commit() {
    asm volatile("cp.async.commit_group;" ::: "memory");
}
template <int N>
__device__ __forceinline__ void cp_wait() {
    asm volatile("cp.async.wait_group %0;" :: "n"(N) : "memory");
}
__device__ __forceinline__ void hmma16816(float d[4], const uint32_t a[4], uint32_t b0, uint32_t b1) {
    asm volatile("mma.sync.aligned.m16n8k16.row.col.f32.f16.f16.f32 "
                 "{%0,%1,%2,%3},{%4,%5,%6,%7},{%8,%9},{%0,%1,%2,%3};"
                 : "+f"(d[0]), "+f"(d[1]), "+f"(d[2]), "+f"(d[3])
                 : "r"(a[0]), "r"(a[1]), "r"(a[2]), "r"(a[3]), "r"(b0), "r"(b1));
}
__device__ __forceinline__ uint32_t pack_h2(float x, float y) {
    __half2 h = __floats2half2_rn(x, y);
    return *reinterpret_cast<uint32_t*>(&h);
}

// ---------------- kernel 0: W fp32 -> fp16, reorder to [128][512] ----------------
__global__ __launch_bounds__(128) void prep_kernel(const float* __restrict__ W) {
    int i = (blockIdx.x * 128 + threadIdx.x) * 2;
    if (i >= 128 * 512) return;
    int n = i >> 9, k = i & 511;
    const float* src = (n < 64) ? (W + n * 1024 + k) : (W + (n - 64) * 1024 + 512 + k);
    float2 v = *(const float2*)src;
    *(__half2*)&g_Bh[i] = __floats2half2_rn(v.x, v.y);
}

// ---------------- kernel 1: persistent P = emb @ B^T, M=256 tiles, 2-stage cp.async ----------------
__global__ __launch_bounds__(512, 1) void gemm_kernel(const float* __restrict__ emb,
                                                      int n_nodes, int ntiles, int grid) {
    extern __shared__ char smem[];
    const uint32_t sb = smem_u32(smem);
    const int tid = threadIdx.x;
    const int lane = tid & 31;
    const int wid = tid >> 5;
    const int wm = wid & 7;     // 8 M-tiles of 32 (CTA M=256)
    const int wn = wid >> 3;    // 2 N-tiles of 64
    const int bid = blockIdx.x;

    const int ntiles_mine = (ntiles - bid + grid - 1) / grid;
    const int gtot = ntiles_mine * 8;

    // producer: global chunk g -> (tile, kchunk), into slot g%2
    auto ISSUE = [&](int g) {
        if (g >= gtot) return;
        const int tile = bid + (g >> 3) * grid;
        const int c = g & 7;
        const int ctaM = tile * 256;
        const uint32_t aBase = sb + (g & 1) * A_STAGE_B;
        const uint32_t bBase = sb + B_OFF + (g & 1) * B_STAGE_B;
        #pragma unroll
        for (int i = 0; i < 8; i++) {           // A: 4096 granules of 16B
            int gr = tid + i * 512;
            int row = gr >> 4, col = gr & 15;
            int ar = ctaM + row;
            if (ar >= n_nodes) ar = n_nodes - 1;
            cp16(aBase + row * (A_PAD * 4) + col * 16,
                 emb + (size_t)ar * N_DIM + c * 64 + col * 4);
        }
        #pragma unroll
        for (int i = 0; i < 2; i++) {           // B: 1024 granules (L2-resident)
            int gr = tid + i * 512;
            int row = gr >> 3, col = gr & 7;
            cp16(bBase + row * (B_PAD * 2) + col * 16,
                 g_Bh + row * N_DIM + c * 64 + col * 8);
        }
    };

    float acc[2][8][4];
    #pragma unroll
    for (int i = 0; i < 2; i++)
        #pragma unroll
        for (int j = 0; j < 8; j++)
            #pragma unroll
            for (int k = 0; k < 4; k++) acc[i][j][k] = 0.0f;

    ISSUE(0); cp_commit();

    const int q = lane & 3;
    const int octr = lane >> 2;

    for (int g = 0; g < gtot; g++) {
        // pending here: exactly {g} (g+1 issued after the barrier below)
        cp_wait<0>();
        __syncthreads();          // stage-g copies visible; all warps done with g-1 -> slot (g+1)%2 free
        ISSUE(g + 1);
        cp_commit();              // overlaps the consume below

        const uint32_t aSlot = (g & 1) * A_STAGE_B;
        const uint32_t bSlot = B_OFF + (g & 1) * B_STAGE_B;
        #pragma unroll
        for (int ks = 0; ks < 4; ks++) {
            // A frags: sigma k-permuted LDS.128 of fp32 + cvt to fp16
            uint32_t afr[2][4];
            #pragma unroll
            for (int mt = 0; mt < 2; mt++) {
                const int r0 = wm * 32 + mt * 16 + octr;
                const float4 v0 = *(const float4*)(smem + aSlot + r0 * (A_PAD * 4) + ks * 64 + q * 16);
                const float4 v1 = *(const float4*)(smem + aSlot + (r0 + 8) * (A_PAD * 4) + ks * 64 + q * 16);
                afr[mt][0] = pack_h2(v0.x, v0.y);
                afr[mt][1] = pack_h2(v1.x, v1.y);
                afr[mt][2] = pack_h2(v0.z, v0.w);
                afr[mt][3] = pack_h2(v1.z, v1.w);
            }
            // B frags: same sigma, one LDS.64 per n8 frag (8 frags = 64 N cols)
            uint2 bfr[8];
            #pragma unroll
            for (int nf = 0; nf < 8; nf++) {
                const int n = wn * 64 + nf * 8 + octr;
                bfr[nf] = *(const uint2*)(smem + bSlot + n * (B_PAD * 2) + ks * 32 + q * 8);
            }
            #pragma unroll
            for (int mt = 0; mt < 2; mt++)
                #pragma unroll
                for (int nf = 0; nf < 8; nf++)
                    hmma16816(acc[mt][nf], afr[mt], bfr[nf].x, bfr[nf].y);
        }

        if ((g & 7) == 7) {
            // epilogue for this tile (overlaps next tile's in-flight copies)
            const int ctaM = (bid + (g >> 3) * grid) * 256;
            #pragma unroll
            for (int mt = 0; mt < 2; mt++) {
                const int r0 = ctaM + wm * 32 + mt * 16 + (lane >> 2);
                const int r1 = r0 + 8;
                #pragma unroll
                for (int nf = 0; nf < 8; nf++) {
                    const int col = wn * 64 + nf * 8 + (lane & 3) * 2;
                    if (r0 < n_nodes)
                        *(float2*)&g_P[(size_t)r0 * 128 + col] = make_float2(acc[mt][nf][0], acc[mt][nf][1]);
                    if (r1 < n_nodes)
                        *(float2*)&g_P[(size_t)r1 * 128 + col] = make_float2(acc[mt][nf][2], acc[mt][nf][3]);
                    acc[mt][nf][0] = acc[mt][nf][1] = acc[mt][nf][2] = acc[mt][nf][3] = 0.0f;
                }
            }
        }
    }
}

// ---------------- kernel 2: per-triple gather-combine, 2 triples/thread ----------------
__global__ __launch_bounds__(256) void gather_kernel(const int* __restrict__ triples,
                                                     const float* __restrict__ b,
                                                     float* __restrict__ out, int n) {
    int t = blockIdx.x * blockDim.x + threadIdx.x;
    int half = (n + 1) >> 1;
    if (t >= half) return;
    int t2 = t + half;
    bool has2 = t2 < n;

    int s1 = triples[t],       r1 = triples[n + t],       o1 = triples[2 * n + t];
    int s2 = 0, r2 = 0, o2 = 0;
    if (has2) { s2 = triples[t2]; r2 = triples[n + t2]; o2 = triples[2 * n + t2]; }

    float a1 = __ldg(&g_P[(size_t)s1 * 128 + r1]);
    float c1 = __ldg(&g_P[(size_t)o1 * 128 + 64 + r1]);
    float a2 = 0.f, c2 = 0.f;
    if (has2) { a2 = __ldg(&g_P[(size_t)s2 * 128 + r2]); c2 = __ldg(&g_P[(size_t)o2 * 128 + 64 + r2]); }

    out[t] = a1 + c1 + __ldg(&b[r1]);
    if (has2) out[t2] = a2 + c2 + __ldg(&b[r2]);
}

extern "C" void kernel_launch(void* const* d_in, const int* in_sizes, int n_in,
                              void* d_out, int out_size)
{
    const float* emb     = (const float*)d_in[0];
    const float* W       = (const float*)d_in[1];
    const float* b       = (const float*)d_in[2];
    const int*   triples = (const int*)d_in[3];
    float*       out     = (float*)d_out;

    int n_nodes = in_sizes[0] / N_DIM;   // 100000
    int n_tr    = in_sizes[3] / 3;       // 200000
    int ntiles  = (n_nodes + 255) / 256;

    static int nsm = 0;
    if (nsm == 0) {
        cudaDeviceGetAttribute(&nsm, cudaDevAttrMultiProcessorCount, 0);
        cudaFuncSetAttribute(gemm_kernel, cudaFuncAttributeMaxDynamicSharedMemorySize, SMEM_BYTES);
    }
    int grid = (ntiles < nsm) ? ntiles : nsm;

    prep_kernel<<<256, 128>>>(W);
    gemm_kernel<<<grid, 512, SMEM_BYTES>>>(emb, n_nodes, ntiles, grid);
    gather_kernel<<<((n_tr + 1) / 2 + 255) / 256, 256>>>(triples, b, out, n_tr);
}

// round 9
// speedup vs baseline: 2.6638x; 1.0379x over previous
#include <cuda_runtime.h>
#include <cuda_fp16.h>
#include <cstdint>

#define N_DIM 512

// ---------------- scratch ----------------
__device__ __half g_Bh[128 * 512];             // fp16 W: rows 0..63 = Ws, 64..127 = Wo
__device__ __half g_P[(size_t)100000 * 128];   // fp16 P: [0..63]=s-scores, [64..127]=o-scores (25.6MB, L2-resident)

// ---------------- smem geometry (2-stage, M=256 tile) ----------------
#define A_PAD 80                               // floats per A row (320B) -> conflict-free LDS.128
#define B_PAD 80                               // halfs per B row (160B)
#define A_STAGE_B (256 * A_PAD * 4)            // 81920
#define B_STAGE_B (128 * B_PAD * 2)            // 20480
#define B_OFF     (2 * A_STAGE_B)              // 163840
#define SMEM_BYTES (2 * A_STAGE_B + 2 * B_STAGE_B)  // 204800

// ---------------- helpers ----------------
__device__ __forceinline__ uint32_t smem_u32(const void* p) {
    uint32_t a;
    asm("{ .reg .u64 t; cvta.to.shared.u64 t, %1; cvt.u32.u64 %0, t; }" : "=r"(a) : "l"(p));
    return a;
}
__device__ __forceinline__ void cp16(uint32_t saddr, const void* g) {
    asm volatile("cp.async.cg.shared.global [%0], [%1], 16;" :: "r"(saddr), "l"(g));
}
__device__ __forceinline__ void cp_commit() {
    asm volatile("cp.async.commit_group;" ::: "memory");
}
template <int N>
__device__ __forceinline__ void cp_wait() {
    asm volatile("cp.async.wait_group %0;" :: "n"(N) : "memory");
}
__device__ __forceinline__ void hmma16816(float d[4], const uint32_t a[4], uint32_t b0, uint32_t b1) {
    asm volatile("mma.sync.aligned.m16n8k16.row.col.f32.f16.f16.f32 "
                 "{%0,%1,%2,%3},{%4,%5,%6,%7},{%8,%9},{%0,%1,%2,%3};"
                 : "+f"(d[0]), "+f"(d[1]), "+f"(d[2]), "+f"(d[3])
                 : "r"(a[0]), "r"(a[1]), "r"(a[2]), "r"(a[3]), "r"(b0), "r"(b1));
}
__device__ __forceinline__ uint32_t pack_h2(float x, float y) {
    __half2 h = __floats2half2_rn(x, y);
    return *reinterpret_cast<uint32_t*>(&h);
}

// ---------------- kernel 0: W fp32 -> fp16, reorder to [128][512] ----------------
__global__ __launch_bounds__(128) void prep_kernel(const float* __restrict__ W) {
    int i = (blockIdx.x * 128 + threadIdx.x) * 2;
    if (i >= 128 * 512) return;
    int n = i >> 9, k = i & 511;
    const float* src = (n < 64) ? (W + n * 1024 + k) : (W + (n - 64) * 1024 + 512 + k);
    float2 v = *(const float2*)src;
    *(__half2*)&g_Bh[i] = __floats2half2_rn(v.x, v.y);
}

// ---------------- kernel 1: persistent P = emb @ B^T, M=256 tiles, 2-stage cp.async ----------------
__global__ __launch_bounds__(512, 1) void gemm_kernel(const float* __restrict__ emb,
                                                      int n_nodes, int ntiles, int grid) {
    extern __shared__ char smem[];
    const uint32_t sb = smem_u32(smem);
    const int tid = threadIdx.x;
    const int lane = tid & 31;
    const int wid = tid >> 5;
    const int wm = wid & 7;     // 8 M-tiles of 32 (CTA M=256)
    const int wn = wid >> 3;    // 2 N-tiles of 64
    const int bid = blockIdx.x;

    const int ntiles_mine = (ntiles - bid + grid - 1) / grid;
    const int gtot = ntiles_mine * 8;

    // producer: global chunk g -> (tile, kchunk), into slot g%2
    auto ISSUE = [&](int g) {
        if (g >= gtot) return;
        const int tile = bid + (g >> 3) * grid;
        const int c = g & 7;
        const int ctaM = tile * 256;
        const uint32_t aBase = sb + (g & 1) * A_STAGE_B;
        const uint32_t bBase = sb + B_OFF + (g & 1) * B_STAGE_B;
        #pragma unroll
        for (int i = 0; i < 8; i++) {           // A: 4096 granules of 16B
            int gr = tid + i * 512;
            int row = gr >> 4, col = gr & 15;
            int ar = ctaM + row;
            if (ar >= n_nodes) ar = n_nodes - 1;
            cp16(aBase + row * (A_PAD * 4) + col * 16,
                 emb + (size_t)ar * N_DIM + c * 64 + col * 4);
        }
        #pragma unroll
        for (int i = 0; i < 2; i++) {           // B: 1024 granules (L2-resident)
            int gr = tid + i * 512;
            int row = gr >> 3, col = gr & 7;
            cp16(bBase + row * (B_PAD * 2) + col * 16,
                 g_Bh + row * N_DIM + c * 64 + col * 8);
        }
    };

    float acc[2][8][4];
    #pragma unroll
    for (int i = 0; i < 2; i++)
        #pragma unroll
        for (int j = 0; j < 8; j++)
            #pragma unroll
            for (int k = 0; k < 4; k++) acc[i][j][k] = 0.0f;

    ISSUE(0); cp_commit();

    const int q = lane & 3;
    const int octr = lane >> 2;

    for (int g = 0; g < gtot; g++) {
        // pending here: exactly {g} (g+1 issued after the barrier below)
        cp_wait<0>();
        __syncthreads();          // stage-g copies visible; all warps done with g-1 -> slot (g+1)%2 free
        ISSUE(g + 1);
        cp_commit();              // overlaps the consume below

        const uint32_t aSlot = (g & 1) * A_STAGE_B;
        const uint32_t bSlot = B_OFF + (g & 1) * B_STAGE_B;
        #pragma unroll
        for (int ks = 0; ks < 4; ks++) {
            // A frags: sigma k-permuted LDS.128 of fp32 + cvt to fp16
            uint32_t afr[2][4];
            #pragma unroll
            for (int mt = 0; mt < 2; mt++) {
                const int r0 = wm * 32 + mt * 16 + octr;
                const float4 v0 = *(const float4*)(smem + aSlot + r0 * (A_PAD * 4) + ks * 64 + q * 16);
                const float4 v1 = *(const float4*)(smem + aSlot + (r0 + 8) * (A_PAD * 4) + ks * 64 + q * 16);
                afr[mt][0] = pack_h2(v0.x, v0.y);
                afr[mt][1] = pack_h2(v1.x, v1.y);
                afr[mt][2] = pack_h2(v0.z, v0.w);
                afr[mt][3] = pack_h2(v1.z, v1.w);
            }
            // B frags: same sigma, one LDS.64 per n8 frag (8 frags = 64 N cols)
            uint2 bfr[8];
            #pragma unroll
            for (int nf = 0; nf < 8; nf++) {
                const int n = wn * 64 + nf * 8 + octr;
                bfr[nf] = *(const uint2*)(smem + bSlot + n * (B_PAD * 2) + ks * 32 + q * 8);
            }
            #pragma unroll
            for (int mt = 0; mt < 2; mt++)
                #pragma unroll
                for (int nf = 0; nf < 8; nf++)
                    hmma16816(acc[mt][nf], afr[mt], bfr[nf].x, bfr[nf].y);
        }

        if ((g & 7) == 7) {
            // epilogue: convert to fp16 and store (4 lanes x half2 = 16B coalesced)
            const int ctaM = (bid + (g >> 3) * grid) * 256;
            #pragma unroll
            for (int mt = 0; mt < 2; mt++) {
                const int r0 = ctaM + wm * 32 + mt * 16 + (lane >> 2);
                const int r1 = r0 + 8;
                #pragma unroll
                for (int nf = 0; nf < 8; nf++) {
                    const int col = wn * 64 + nf * 8 + (lane & 3) * 2;
                    if (r0 < n_nodes)
                        *(uint32_t*)&g_P[(size_t)r0 * 128 + col] = pack_h2(acc[mt][nf][0], acc[mt][nf][1]);
                    if (r1 < n_nodes)
                        *(uint32_t*)&g_P[(size_t)r1 * 128 + col] = pack_h2(acc[mt][nf][2], acc[mt][nf][3]);
                    acc[mt][nf][0] = acc[mt][nf][1] = acc[mt][nf][2] = acc[mt][nf][3] = 0.0f;
                }
            }
        }
    }
}

// ---------------- kernel 2: per-triple gather-combine, 2 triples/thread, fp16 P (L2-resident) ----------------
__global__ __launch_bounds__(256) void gather_kernel(const int* __restrict__ triples,
                                                     const float* __restrict__ b,
                                                     float* __restrict__ out, int n) {
    int t = blockIdx.x * blockDim.x + threadIdx.x;
    int half = (n + 1) >> 1;
    if (t >= half) return;
    int t2 = t + half;
    bool has2 = t2 < n;

    int s1 = triples[t],  r1 = triples[n + t],  o1 = triples[2 * n + t];
    int s2 = 0, r2 = 0, o2 = 0;
    if (has2) { s2 = triples[t2]; r2 = triples[n + t2]; o2 = triples[2 * n + t2]; }

    __half a1 = __ldg(&g_P[(size_t)s1 * 128 + r1]);
    __half c1 = __ldg(&g_P[(size_t)o1 * 128 + 64 + r1]);
    __half a2 = __float2half(0.f), c2 = __float2half(0.f);
    if (has2) {
        a2 = __ldg(&g_P[(size_t)s2 * 128 + r2]);
        c2 = __ldg(&g_P[(size_t)o2 * 128 + 64 + r2]);
    }

    out[t] = __half2float(a1) + __half2float(c1) + __ldg(&b[r1]);
    if (has2) out[t2] = __half2float(a2) + __half2float(c2) + __ldg(&b[r2]);
}

extern "C" void kernel_launch(void* const* d_in, const int* in_sizes, int n_in,
                              void* d_out, int out_size)
{
    const float* emb     = (const float*)d_in[0];
    const float* W       = (const float*)d_in[1];
    const float* b       = (const float*)d_in[2];
    const int*   triples = (const int*)d_in[3];
    float*       out     = (float*)d_out;

    int n_nodes = in_sizes[0] / N_DIM;   // 100000
    int n_tr    = in_sizes[3] / 3;       // 200000
    int ntiles  = (n_nodes + 255) / 256;

    static int nsm = 0;
    if (nsm == 0) {
        cudaDeviceGetAttribute(&nsm, cudaDevAttrMultiProcessorCount, 0);
        cudaFuncSetAttribute(gemm_kernel, cudaFuncAttributeMaxDynamicSharedMemorySize, SMEM_BYTES);
    }
    int grid = (ntiles < nsm) ? ntiles : nsm;

    prep_kernel<<<256, 128>>>(W);
    gemm_kernel<<<grid, 512, SMEM_BYTES>>>(emb, n_nodes, ntiles, grid);
    gather_kernel<<<((n_tr + 1) / 2 + 255) / 256, 256>>>(triples, b, out, n_tr);
}